// round 2
// baseline (speedup 1.0000x reference)
#include <cuda_runtime.h>
#include <cuda_bf16.h>

// Problem constants (fixed by setup_inputs)
#define BB    8
#define CC    64
#define NPTS  65536
#define RR    32
#define R3    (RR*RR*RR)           // 32768
#define NVOX  (BB*R3)              // 262144
#define VOX_ELEMS  (BB*CC*R3)      // 16777216
#define NORM_ELEMS (BB*3*NPTS)     // 1572864

// Scratch (device globals: zero-initialized at module load; finalize re-zeroes
// sums/cnt each launch so every graph replay starts clean).
__device__ float g_sums[(size_t)NVOX * CC];   // [b*R3+vox][C]  (64 MB, L2-resident)
__device__ float g_cnt[NVOX];
__device__ int   g_idx[BB * NPTS];

// ---------------------------------------------------------------------------
// Kernel 1: per-point quantization. Writes norm_coords, voxel index, counts.
// ---------------------------------------------------------------------------
__global__ void point_kernel(const float* __restrict__ coords,
                             float* __restrict__ norm_out) {
    int tid = blockIdx.x * blockDim.x + threadIdx.x;   // exactly B*N threads
    int b = tid >> 16;            // N = 65536
    int n = tid & (NPTS - 1);

    const float* cb = coords + (size_t)b * 3 * NPTS + n;
    float x = cb[0];
    float y = cb[NPTS];
    float z = cb[2 * NPTS];

    // clip(coords * r, 0, r-1)  — exact match to jnp.clip
    float nx = fminf(fmaxf(x * (float)RR, 0.0f), (float)(RR - 1));
    float ny = fminf(fmaxf(y * (float)RR, 0.0f), (float)(RR - 1));
    float nz = fminf(fmaxf(z * (float)RR, 0.0f), (float)(RR - 1));

    if (norm_out) {
        float* nb = norm_out + (size_t)b * 3 * NPTS + n;
        nb[0]        = nx;
        nb[NPTS]     = ny;
        nb[2 * NPTS] = nz;
    }

    // jnp.round == round-half-to-even == cvt.rni
    int vx = __float2int_rn(nx);
    int vy = __float2int_rn(ny);
    int vz = __float2int_rn(nz);

    int gidx = b * R3 + (vx * RR + vy) * RR + vz;
    g_idx[tid] = gidx;
    atomicAdd(&g_cnt[gidx], 1.0f);   // compiles to REDG (result unused)
}

// ---------------------------------------------------------------------------
// Kernel 2: feature scatter. Thread = (b, c4, n); 4 channels per thread via
// red.global.add.v4.f32 (one 16B reduction instead of 4 scalar atomics).
// ---------------------------------------------------------------------------
__global__ void scatter_kernel(const float* __restrict__ feats) {
    int tid  = blockIdx.x * 256 + threadIdx.x;  // exactly B*(C/4)*N threads
    int n    = tid & (NPTS - 1);
    int rest = tid >> 16;
    int c4   = rest & 15;
    int b    = rest >> 4;

    int gidx = g_idx[(b << 16) | n];            // coalesced, L2-hit across c4

    const float* f = feats + ((size_t)(b * CC + c4 * 4)) * NPTS + n;
    float f0 = f[0];
    float f1 = f[(size_t)NPTS];
    float f2 = f[(size_t)2 * NPTS];
    float f3 = f[(size_t)3 * NPTS];

    float* dst = &g_sums[(size_t)gidx * CC + c4 * 4];   // 16B aligned
    asm volatile("red.global.add.v4.f32 [%0], {%1, %2, %3, %4};"
                 :: "l"(dst), "f"(f0), "f"(f1), "f"(f2), "f"(f3)
                 : "memory");
}

// ---------------------------------------------------------------------------
// Kernel 3: finalize. Block = 64 voxels x 64 channels; smem transpose
// ([64][65] pad -> conflict-free), divide by count, coalesced [C][vox] write.
// Re-zeroes its slice of g_sums / g_cnt for the next graph replay.
// ---------------------------------------------------------------------------
__global__ void finalize_kernel(float* __restrict__ out) {
    __shared__ float s[64 * 65];
    __shared__ float sinv[64];

    int gv0 = blockIdx.x * 64;      // global voxel base (contiguous within a batch)
    int t   = threadIdx.x;          // 256 threads

    float4* gp = reinterpret_cast<float4*>(g_sums + (size_t)gv0 * CC);
    const float4 zero4 = make_float4(0.f, 0.f, 0.f, 0.f);

    #pragma unroll
    for (int it = 0; it < 4; it++) {
        int j4 = it * 256 + t;          // 1024 float4 = 4096 floats
        float4 v = gp[j4];
        int j  = j4 * 4;
        int vv = j >> 6;                // voxel within tile
        int cc = j & 63;                // channel
        float* sp = &s[vv * 65 + cc];
        sp[0] = v.x; sp[1] = v.y; sp[2] = v.z; sp[3] = v.w;
        gp[j4] = zero4;                 // reset for next replay
    }
    if (t < 64) {
        float c = g_cnt[gv0 + t];
        sinv[t] = 1.0f / fmaxf(c, 1.0f);
        g_cnt[gv0 + t] = 0.0f;
    }
    __syncthreads();

    int b     = gv0 >> 15;              // / R3
    int vbase = gv0 & (R3 - 1);

    #pragma unroll
    for (int it = 0; it < 16; it++) {
        int c  = it * 4 + (t >> 6);
        int vl = t & 63;
        out[((size_t)(b * CC + c)) * R3 + vbase + vl] = s[vl * 65 + c] * sinv[vl];
    }
}

// ---------------------------------------------------------------------------
extern "C" void kernel_launch(void* const* d_in, const int* in_sizes, int n_in,
                              void* d_out, int out_size) {
    const float* feats  = (const float*)d_in[0];   // [B, C, N]
    const float* coords = (const float*)d_in[1];   // [B, 3, N]
    float* out = (float*)d_out;

    float* norm_out = (out_size >= VOX_ELEMS + NORM_ELEMS) ? (out + VOX_ELEMS)
                                                           : nullptr;

    point_kernel<<<(BB * NPTS) / 256, 256>>>(coords, norm_out);
    scatter_kernel<<<(BB * (CC / 4) * NPTS) / 256, 256>>>(feats);
    finalize_kernel<<<NVOX / 64, 256>>>(out);
}